// round 6
// baseline (speedup 1.0000x reference)
#include <cuda_runtime.h>

#define BB 8192
#define TT 512
#define KK 12

#define GPW 6                        // batch groups per warp (5 lanes each)
#define WPB 5                        // warps per block
#define GPB (GPW * WPB)              // 30 batches per block
#define FWD_THREADS (WPB * 32)       // 160
#define NBLK ((BB + GPB - 1) / GPB)  // 274 (tail groups duplicate batch BB-1)
#define AMASK 0x3fffffffu            // lanes 0..29 active

#define BT_WPB 8                     // btr warps per block
#define BT_THREADS (BT_WPB * 32)
#define BT_NBLK (BB / 4 / BT_WPB)    // 2048 warps, 4 batches per warp

typedef unsigned long long u64;

// Packed backpointers: row (t,b) = u64; nibble j = best prev tag for tag j at t.
__device__ u64 g_bp[(size_t)TT * BB];   // 33.5 MB
// Final trellis row values, [B][12] floats (slot 10 = -1e30 sentinel).
__device__ float g_final[(size_t)BB * KK];
__device__ float g_scores_scratch[BB];

// ---------------------------------------------------------------------------
// f32x2 packed helpers. add.rn.f32x2 is bit-exact vs scalar FADD RN.
// ---------------------------------------------------------------------------
__device__ __forceinline__ u64 pack2(float lo, float hi) {
    u64 r;
    asm("mov.b64 %0, {%1, %2};" : "=l"(r) : "f"(lo), "f"(hi));
    return r;
}
__device__ __forceinline__ void unpack2(u64 v, float& lo, float& hi) {
    asm("mov.b64 {%0, %1}, %2;" : "=f"(lo), "=f"(hi) : "l"(v));
}
__device__ __forceinline__ u64 add2(u64 a, u64 b) {
    u64 r;
    asm("add.rn.f32x2 %0, %1, %2;" : "=l"(r) : "l"(a), "l"(b));
    return r;
}

// ---------------------------------------------------------------------------
// First-index-wins select (matches jnp.argmax): >= keeps left; every merge's
// left operand covers strictly smaller indices.
// ---------------------------------------------------------------------------
__device__ __forceinline__ void sel2(float a, int ia, float b, int ib,
                                     float& ov, int& oi) {
    bool p = (a >= b);
    ov = p ? a : b;
    oi = p ? ia : ib;
}

// argmax over candidates 0..9 (i=10,11 provably never win for t>=2).
__device__ __forceinline__ void amax10(const float* v, float& bv, int& bi) {
    float s0, s1, s2, s3, s4;
    int   i0, i1, i2, i3, i4;
    sel2(v[0], 0, v[1], 1, s0, i0);
    sel2(v[2], 2, v[3], 3, s1, i1);
    sel2(v[4], 4, v[5], 5, s2, i2);
    sel2(v[6], 6, v[7], 7, s3, i3);
    sel2(v[8], 8, v[9], 9, s4, i4);
    float t0, t1; int k0, k1;
    sel2(s0, i0, s1, i1, t0, k0);
    sel2(s2, i2, s3, i3, t1, k1);
    float u; int ku;
    sel2(t0, k0, t1, k1, u, ku);
    sel2(u, ku, s4, i4, bv, bi);
}

__device__ __forceinline__ void amax12(const float* v, float& bv, int& bi) {
    float s0, s1, s2, s3, s4, s5;
    int   i0, i1, i2, i3, i4, i5;
    sel2(v[0],  0,  v[1],  1,  s0, i0);
    sel2(v[2],  2,  v[3],  3,  s1, i1);
    sel2(v[4],  4,  v[5],  5,  s2, i2);
    sel2(v[6],  6,  v[7],  7,  s3, i3);
    sel2(v[8],  8,  v[9],  9,  s4, i4);
    sel2(v[10], 10, v[11], 11, s5, i5);
    float t0, t1, t2; int k0, k1, k2;
    sel2(s0, i0, s1, i1, t0, k0);
    sel2(s2, i2, s3, i3, t1, k1);
    sel2(s4, i4, s5, i5, t2, k2);
    float u; int ku;
    sel2(t0, k0, t1, k1, u, ku);
    sel2(u, ku, t2, k2, bv, bi);
}

// ---------------------------------------------------------------------------
// Forward: 5 lanes per batch (2 tags each), 6 batches per warp, warp-local
// smem exchange (__syncwarp only). Packed f32x2 adds. 4-deep emission prefetch
// (covers DRAM latency). Tag chains j=0..9; j=11 once at t=511; j=10 never.
// ---------------------------------------------------------------------------
__global__ __launch_bounds__(FWD_THREADS) void viterbi_fwd(
    const float* __restrict__ logits,   // [B, T, K]
    const float* __restrict__ trans)    // [K, K], trans[i*K+j] = i -> j
{
    __shared__ __align__(16) float buf[2][GPB][12];   // 48B rows

    const int lane = threadIdx.x & 31;
    const int wid = threadIdx.x >> 5;
    if (lane >= 30) return;
    const int gl = lane / 5;
    const int k = lane - gl * 5;             // tags 2k, 2k+1
    const int g = wid * GPW + gl;
    size_t b = (size_t)blockIdx.x * GPB + g;
    if (b >= BB) b = BB - 1;                 // tail duplicates (same-value writes)
    const int j0 = 2 * k;

    u64 tcc0[5], tcc1[5];
#pragma unroll
    for (int i = 0; i < 5; i++) {
        tcc0[i] = pack2(__ldg(trans + (2 * i) * KK + j0),
                        __ldg(trans + (2 * i + 1) * KK + j0));
        tcc1[i] = pack2(__ldg(trans + (2 * i) * KK + j0 + 1),
                        __ldg(trans + (2 * i + 1) * KK + j0 + 1));
    }
    const float tca = __ldg(trans + 10 * KK + j0);      // t=1-only candidate i=10
    const float tcb = __ldg(trans + 10 * KK + j0 + 1);
    float tcl[10];
    if (k == 0) {
#pragma unroll
        for (int i = 0; i < 10; i++) tcl[i] = __ldg(trans + i * KK + 11);
    }

    const float* em = logits + b * TT * KK;
    unsigned char* bp8 = (unsigned char*)g_bp;

    // t=0 row = emissions
    {
        float2 e0 = __ldg((const float2*)(em + j0));
        *(float2*)&buf[0][g][j0] = e0;
        if (k == 0) buf[0][g][10] = __ldg(em + 10);
    }
    // 4-deep emission prefetch queue: en[i] holds emission for t = 1+i
    float2 en[4];
#pragma unroll
    for (int i = 0; i < 4; i++)
        en[i] = __ldg((const float2*)(em + (size_t)(1 + i) * KK + j0));
    __syncwarp(AMASK);

    float best0, best1;

    // ---- peeled t = 1: candidates i = 0..10 ----
    {
        const u64* rp = (const u64*)&buf[0][g][0];
        u64 r0 = rp[0], r1 = rp[1], r2 = rp[2], r3 = rp[3], r4 = rp[4];
        const float em10 = buf[0][g][10];
        const float ex = en[0].x, ey = en[0].y;
        en[0] = __ldg((const float2*)(em + (size_t)5 * KK + j0));

        float v[10], w[10];
        unpack2(add2(r0, tcc0[0]), v[0], v[1]);
        unpack2(add2(r1, tcc0[1]), v[2], v[3]);
        unpack2(add2(r2, tcc0[2]), v[4], v[5]);
        unpack2(add2(r3, tcc0[3]), v[6], v[7]);
        unpack2(add2(r4, tcc0[4]), v[8], v[9]);
        unpack2(add2(r0, tcc1[0]), w[0], w[1]);
        unpack2(add2(r1, tcc1[1]), w[2], w[3]);
        unpack2(add2(r2, tcc1[2]), w[4], w[5]);
        unpack2(add2(r3, tcc1[3]), w[6], w[7]);
        unpack2(add2(r4, tcc1[4]), w[8], w[9]);

        float m0, m1; int a0, a1;
        amax10(v, m0, a0);
        amax10(w, m1, a1);
        sel2(m0, a0, em10 + tca, 10, m0, a0);
        sel2(m1, a1, em10 + tcb, 10, m1, a1);

        best0 = m0 + ex;
        best1 = m1 + ey;
        *(float2*)&buf[1][g][j0] = make_float2(best0, best1);
        bp8[((size_t)1 * BB + b) * 8 + k] = (unsigned char)(a0 | (a1 << 4));
    }

    // ---- main loop t = 2..511 ----
#pragma unroll 4
    for (int t = 2; t < TT; t++) {
        __syncwarp(AMASK);
        const float* rr = &buf[(t - 1) & 1][g][0];
        float4 f0 = *(const float4*)(rr);
        float4 f1 = *(const float4*)(rr + 4);
        u64 r4x = *(const u64*)(rr + 8);
        u64 r0 = pack2(f0.x, f0.y), r1 = pack2(f0.z, f0.w);
        u64 r2 = pack2(f1.x, f1.y), r3 = pack2(f1.z, f1.w);

        const int slot = (t - 1) & 3;
        const float ex = en[slot].x, ey = en[slot].y;
        const int tn = (t + 4 < TT) ? (t + 4) : (TT - 1);
        en[slot] = __ldg((const float2*)(em + (size_t)tn * KK + j0));

        float v[10], w[10];
        unpack2(add2(r0, tcc0[0]), v[0], v[1]);
        unpack2(add2(r1, tcc0[1]), v[2], v[3]);
        unpack2(add2(r2, tcc0[2]), v[4], v[5]);
        unpack2(add2(r3, tcc0[3]), v[6], v[7]);
        unpack2(add2(r4x, tcc0[4]), v[8], v[9]);
        unpack2(add2(r0, tcc1[0]), w[0], w[1]);
        unpack2(add2(r1, tcc1[1]), w[2], w[3]);
        unpack2(add2(r2, tcc1[2]), w[4], w[5]);
        unpack2(add2(r3, tcc1[3]), w[6], w[7]);
        unpack2(add2(r4x, tcc1[4]), w[8], w[9]);

        float m0, m1; int a0, a1;
        amax10(v, m0, a0);
        amax10(w, m1, a1);

        best0 = m0 + ex;
        best1 = m1 + ey;
        *(float2*)&buf[t & 1][g][j0] = make_float2(best0, best1);
        bp8[((size_t)t * BB + b) * 8 + k] = (unsigned char)(a0 | (a1 << 4));
    }

    *(float2*)(g_final + b * KK + j0) = make_float2(best0, best1);

    // lane 0: tag 11 at t=511 from row 510 (buf[0], synced at top of t=511)
    if (k == 0) {
        const u64* rp = (const u64*)&buf[0][g][0];
        float p[10];
        unpack2(rp[0], p[0], p[1]);
        unpack2(rp[1], p[2], p[3]);
        unpack2(rp[2], p[4], p[5]);
        unpack2(rp[3], p[6], p[7]);
        unpack2(rp[4], p[8], p[9]);
        float c[10];
#pragma unroll
        for (int i = 0; i < 10; i++) c[i] = p[i] + tcl[i];
        float m11; int a11;
        amax10(c, m11, a11);
        float b11 = m11 + __ldg(em + (size_t)(TT - 1) * KK + 11);
        *(float2*)(g_final + b * KK + 10) = make_float2(-1e30f, b11);
        bp8[((size_t)(TT - 1) * BB + b) * 8 + 5] = (unsigned char)(a11 << 4);
    }
}

// ---------------------------------------------------------------------------
// Backtrace via parallel function composition (bit-exact integer scan).
// Warp = 4 batches; 8 lanes per batch. Lane (trow) owns 64 bp rows; builds a
// 10-entry tag->tag map, 3 shfl-compose levels give each lane its entry tag,
// then a re-walk emits path values. No T-long dependent chain.
// ---------------------------------------------------------------------------
#define IDENT_MAP 0x9876543210ull

__device__ __forceinline__ int nib(u64 m, int e) {
    return (int)((m >> (e << 2)) & 15ull);
}

__global__ __launch_bounds__(BT_THREADS) void viterbi_btr(
    float* __restrict__ scores,   // [B]
    float* __restrict__ paths)    // [B, T] as float
{
    const int lane = threadIdx.x & 31;
    const int wid = threadIdx.x >> 5;
    const int trow = lane >> 2;             // 0..7
    const int bofs = lane & 3;              // 0..3
    const int warp_global = blockIdx.x * BT_WPB + wid;
    const size_t b = (size_t)warp_global * 4 + bofs;
    const u64* bp = g_bp;

    // final argmax (each lane computes for its own batch; broadcast loads)
    float v[12];
    {
        const float4* row = (const float4*)(g_final + b * KK);
        float4 r0 = __ldg(&row[0]), r1 = __ldg(&row[1]), r2 = __ldg(&row[2]);
        v[0] = r0.x; v[1] = r0.y; v[2]  = r0.z; v[3]  = r0.w;
        v[4] = r1.x; v[5] = r1.y; v[6]  = r1.z; v[7]  = r1.w;
        v[8] = r2.x; v[9] = r2.y; v[10] = r2.z; v[11] = r2.w;
    }
    float bv; int last;
    amax12(v, bv, last);

    // path[510] from row 511 (handles last == 11 via its special nibble)
    const u64 row511 = __ldg(bp + (size_t)511 * BB + b);
    const int cur510 = nib(row511, last);

    if (trow == 0) {
        scores[b] = bv;
        paths[b * TT + 511] = (float)last;
        paths[b * TT + 510] = (float)cur510;
    }

    // chunk of rows: t = t_hi .. t_hi-63 (trow 7: only 62 valid rows, down to t=1)
    const int t_hi = 510 - 64 * trow;
    const int nrows = (trow < 7) ? 64 : 62;

    // ---- pass 1: build 10-entry map over the chunk ----
    int m[10];
#pragma unroll
    for (int e = 0; e < 10; e++) m[e] = e;

    for (int base = 0; base < 64; base += 8) {
        u64 r[8];
#pragma unroll
        for (int q = 0; q < 8; q++) {
            const int i = base + q;
            r[q] = (i < nrows) ? __ldg(bp + (size_t)(t_hi - i) * BB + b)
                               : IDENT_MAP;
        }
#pragma unroll
        for (int q = 0; q < 8; q++) {
#pragma unroll
            for (int e = 0; e < 10; e++) m[e] = nib(r[q], m[e]);
        }
    }

    // pack map
    u64 S = 0;
#pragma unroll
    for (int e = 0; e < 10; e++) S |= (u64)m[e] << (e << 2);

    // ---- inclusive scan over the 8-lane group (compose: apply prev, then self)
#pragma unroll
    for (int d = 1; d <= 4; d <<= 1) {
        u64 P = __shfl_up_sync(0xffffffffu, S, 4 * d);
        if (trow >= d) {
            u64 Tm = 0;
#pragma unroll
            for (int e = 0; e < 10; e++) {
                int ne = nib(P, e);
                Tm |= (u64)nib(S, ne) << (e << 2);
            }
            S = Tm;
        }
    }

    // exclusive: entry tag for this lane
    u64 X = __shfl_up_sync(0xffffffffu, S, 4);
    int cur = (trow == 0) ? cur510 : nib(X, cur510);

    // ---- pass 2: re-walk (rows hit L2) and emit path values ----
    float* po = paths + b * TT;
    u64 q0[8], q1[8];
#pragma unroll
    for (int q = 0; q < 8; q++)
        q0[q] = (q < nrows) ? __ldg(bp + (size_t)(t_hi - q) * BB + b) : IDENT_MAP;
#pragma unroll
    for (int q = 0; q < 8; q++) {
        const int i = 8 + q;
        q1[q] = (i < nrows) ? __ldg(bp + (size_t)(t_hi - i) * BB + b) : IDENT_MAP;
    }

    for (int base = 0; base < 64; base += 8) {
#pragma unroll
        for (int q = 0; q < 8; q++) {
            const int i = base + q;
            cur = nib(q0[q], cur);
            if (i < nrows) po[t_hi - i - 1] = (float)cur;
        }
#pragma unroll
        for (int q = 0; q < 8; q++) q0[q] = q1[q];
        if (base + 16 < 64) {
#pragma unroll
            for (int q = 0; q < 8; q++) {
                const int i = base + 16 + q;
                q1[q] = (i < nrows) ? __ldg(bp + (size_t)(t_hi - i) * BB + b)
                                    : IDENT_MAP;
            }
        }
    }
}

// ---------------------------------------------------------------------------
// Launch
// ---------------------------------------------------------------------------
extern "C" void kernel_launch(void* const* d_in, const int* in_sizes, int n_in,
                              void* d_out, int out_size) {
    const float* logits = (const float*)d_in[0];
    const float* trans  = (const float*)d_in[1];
    if (n_in >= 2 && in_sizes[0] == KK * KK) {  // robustness: swapped inputs
        const float* tmp = logits; logits = trans; trans = tmp;
    }

    viterbi_fwd<<<NBLK, FWD_THREADS>>>(logits, trans);

    float* out = (float*)d_out;
    float* scores;
    float* paths;
    float* d_scores_scratch = nullptr;
    cudaGetSymbolAddress((void**)&d_scores_scratch, g_scores_scratch);

    if (out_size >= BB * TT + BB) {
        scores = out;            // [scores (B) | paths (B*T)]
        paths = out + BB;
    } else if (out_size == BB * TT) {
        scores = d_scores_scratch;
        paths = out;
    } else {
        scores = out;
        float* d_bp = nullptr;
        cudaGetSymbolAddress((void**)&d_bp, g_bp);
        paths = (float*)d_bp;    // dead scratch as sink
    }

    viterbi_btr<<<BT_NBLK, BT_THREADS>>>(scores, paths);
}